// round 16
// baseline (speedup 1.0000x reference)
#include <cuda_runtime.h>
#include <cstdint>

#define C 512
#define NBINS 256
#define RPB 8
#define LIST_CAP 64    // small fast-path list; exact global fallback if exceeded

// k thresholds for C=512: int(C/2), int(C*2/3), int(C*3/4), int(C*4/5)
#define K1 256u
#define K2 341u
#define K3 384u
#define K4 409u

// Fixed-exponent quantization: y = x + 1.5*2^16 has ulp = 1/128.
// 256 bins cover x in [-1.4921875, 0.5); all 4 rank boundaries for this
// problem sit deep inside. Exactness never depends on bin quality.
#define OFFF 98304.0f
#define TOPB 0x47C00040u   // bits(98304.5f)

// Monotone 32-bit key: larger float -> larger key. (Boundary elems only.)
__device__ __forceinline__ unsigned int mono_key(float x)
{
    unsigned int u = __float_as_uint(x);
    return u ^ (((unsigned int)((int)u >> 31)) | 0x80000000u);
}

// zero-byte detector: 0x80 set in each byte of t that is zero
#define ZB(t) ((((t) - 0x01010101u) & ~(t)) & 0x80808080u)

__global__ __launch_bounds__(32 * RPB, 5)
void multiscale_topk_kernel(const float* __restrict__ attn,
                            const float* __restrict__ w1p,
                            const float* __restrict__ w2p,
                            const float* __restrict__ w3p,
                            const float* __restrict__ w4p,
                            float* __restrict__ out)
{
    __shared__ unsigned int       cnt[RPB][NBINS];
    __shared__ unsigned long long list[RPB][LIST_CAP];
    __shared__ unsigned int       listN[RPB];
    __shared__ uint4              bbs[RPB];          // per k: (bin<<16) | G
    __shared__ unsigned char      ovr[RPB][C];       // membership bits per amb elem

    const int lane = threadIdx.x & 31;
    const int wrow = threadIdx.x >> 5;
    const int row  = blockIdx.x * RPB + wrow;
    const float* __restrict__ rp = attn + (size_t)row * C;

    const float YLO = __uint_as_float(TOPB - 255u);
    const float YHI = __uint_as_float(TOPB);

    // ---- init ----
    {
        uint4 z = make_uint4(0u, 0u, 0u, 0u);
        *(uint4*)&cnt[wrow][lane * 8]     = z;
        *(uint4*)&cnt[wrow][lane * 8 + 4] = z;
        if (lane == 0) listN[wrow] = 0u;
    }

    // ---- load 16 elems / lane (coalesced float4) ----
    float4 X[4];
    #pragma unroll
    for (int g = 0; g < 4; g++)
        X[g] = ((const float4*)rp)[lane + 32 * g];

    __syncwarp();

    // ---- pass A: float-clamped exact-bit bins + count histogram ----
    unsigned int binw[4];
    {
        const unsigned int sel[4] = {0u, 0x3240u, 0x3410u, 0x4210u};
        const float* xv = (const float*)X;
        #pragma unroll
        for (int g = 0; g < 4; g++) {
            unsigned int bw = 0u;
            #pragma unroll
            for (int e = 0; e < 4; e++) {
                float yc = fminf(fmaxf(xv[4 * g + e] + OFFF, YLO), YHI);
                unsigned int b = TOPB - __float_as_uint(yc);   // 0..255 exact
                bw = (e == 0) ? b : __byte_perm(bw, b, sel[e]);
                atomicAdd(&cnt[wrow][b], 1u);
            }
            binw[g] = bw;
        }
    }
    __syncwarp();

    // ---- scan 256 bins; locate the 4 boundary bins (G < k <= G+cnt) ----
    {
        uint4 c0 = *(uint4*)&cnt[wrow][lane * 8];
        uint4 c1 = *(uint4*)&cnt[wrow][lane * 8 + 4];
        unsigned int cc[8] = {c0.x, c0.y, c0.z, c0.w, c1.x, c1.y, c1.z, c1.w};
        unsigned int tot = 0u;
        #pragma unroll
        for (int j = 0; j < 8; j++) tot += cc[j];
        unsigned int ti = tot;
        #pragma unroll
        for (int d = 1; d < 32; d <<= 1) {
            unsigned int v = __shfl_up_sync(0xffffffffu, ti, d);
            if (lane >= d) ti += v;
        }
        unsigned int run = ti - tot;               // exclusive prefix
        #pragma unroll
        for (int j = 0; j < 8; j++) {
            unsigned int G = run, E = run + cc[j];
            if (G < K4 && E >= K1) {
                unsigned int w = ((unsigned int)(lane * 8 + j) << 16) | G;
                if (G < K1 && E >= K1) bbs[wrow].x = w;
                if (G < K2 && E >= K2) bbs[wrow].y = w;
                if (G < K3 && E >= K3) bbs[wrow].z = w;
                if (G < K4 && E >= K4) bbs[wrow].w = w;
            }
            run = E;
        }
    }
    __syncwarp();

    // ---- selection stage: bk/gg live only here ----
    float s1 = 0.f, s2 = 0.f, s3 = 0.f, s4 = 0.f;
    unsigned int ambm = 0u;
    {
        const uint4 B = bbs[wrow];
        const unsigned int bk1 = B.x >> 16, bk2 = B.y >> 16,
                           bk3 = B.z >> 16, bk4 = B.w >> 16;

        // vectorized amb detection (bin byte == some boundary bin)
        {
            const unsigned int k1x4 = bk1 * 0x01010101u;
            const unsigned int k2x4 = bk2 * 0x01010101u;
            const unsigned int k3x4 = bk3 * 0x01010101u;
            const unsigned int k4x4 = bk4 * 0x01010101u;
            #pragma unroll
            for (int g = 0; g < 4; g++) {
                unsigned int w = binw[g];
                unsigned int z = ZB(w ^ k1x4) | ZB(w ^ k2x4) | ZB(w ^ k3x4) | ZB(w ^ k4x4);
                ambm |= ((((z >> 7) * 0x01020408u) >> 24) & 0xFu) << (4 * g);
            }
        }

        // gather boundary candidates (x live in X; ~6 per row)
        {
            const float* xv = (const float*)X;
            unsigned int am = ambm;
            while (am) {
                int i = __ffs(am) - 1; am &= am - 1;
                int gidx = 4 * lane + 128 * (i >> 2) + (i & 3);
                unsigned int b = (binw[i >> 2] >> (8 * (i & 3))) & 255u;
                unsigned long long key = ((unsigned long long)b << 48)
                    | ((unsigned long long)mono_key(xv[i]) << 16)
                    | (unsigned long long)(65535u - (unsigned int)gidx);
                unsigned int pos = atomicAdd(&listN[wrow], 1u);
                if (pos < LIST_CAP) list[wrow][pos] = key;
            }
        }
        __syncwarp();

        const unsigned int gg1 = B.x & 0xFFFFu, gg2 = B.y & 0xFFFFu,
                           gg3 = B.z & 0xFFFFu, gg4 = B.w & 0xFFFFu;
        const unsigned int M = listN[wrow];
        if (M <= LIST_CAP) {
            // exact rank per candidate -> membership bits + sum deltas
            for (unsigned int j = lane; j < M; j += 32) {
                unsigned long long cj = list[wrow][j];
                unsigned int hb = (unsigned int)(cj >> 48);
                unsigned int g0 = (hb == bk1) ? gg1 : (hb == bk2) ? gg2
                                : (hb == bk3) ? gg3 : gg4;
                unsigned int r = g0;
                for (unsigned int q = 0u; q < M; q++) {
                    unsigned long long cq = list[wrow][q];
                    r += (unsigned int)((cq > cj) && ((unsigned int)(cq >> 48) == hb));
                }
                // recover x and exp from the key (exact bit inverse of mono_key)
                unsigned int mk = (unsigned int)(cj >> 16);
                float x = __uint_as_float((mk & 0x80000000u) ? (mk & 0x7FFFFFFFu) : ~mk);
                float e = __expf(x);
                bool i1 = (hb < bk1) | ((hb == bk1) & (r < K1));
                bool i2 = (hb < bk2) | ((hb == bk2) & (r < K2));
                bool i3 = (hb < bk3) | ((hb == bk3) & (r < K3));
                bool i4 = (hb < bk4) | ((hb == bk4) & (r < K4));
                if ((hb == bk1) & (r < K1)) s1 += e;
                if ((hb == bk2) & (r < K2)) s2 += e;
                if ((hb == bk3) & (r < K3)) s3 += e;
                if ((hb == bk4) & (r < K4)) s4 += e;
                unsigned int gidx = 65535u - (unsigned int)(cj & 0xFFFFu);
                ovr[wrow][gidx] = (unsigned char)((unsigned)i1 | ((unsigned)i2 << 1)
                                | ((unsigned)i3 << 2) | ((unsigned)i4 << 3));
            }
        } else if (ambm) {
            // Exact fallback (adversarial only): rank own amb elems by
            // scanning the full row from global. O(C) per amb elem.
            const float* xv = (const float*)X;
            unsigned int am = ambm;
            while (am) {
                int i = __ffs(am) - 1; am &= am - 1;
                float x = xv[i];
                int gidx = 4 * lane + 128 * (i >> 2) + (i & 3);
                unsigned int b = (binw[i >> 2] >> (8 * (i & 3))) & 255u;
                unsigned long long key = ((unsigned long long)mono_key(x) << 16)
                    | (unsigned long long)(65535u - (unsigned int)gidx);
                unsigned int g0 = (b == bk1) ? gg1 : (b == bk2) ? gg2
                                : (b == bk3) ? gg3 : gg4;
                unsigned int r = g0;
                for (int j = 0; j < C; j++) {
                    float xj = __ldg(rp + j);
                    float ycj = fminf(fmaxf(xj + OFFF, YLO), YHI);
                    unsigned int bj = TOPB - __float_as_uint(ycj);
                    unsigned long long kj = ((unsigned long long)mono_key(xj) << 16)
                        | (unsigned long long)(65535u - (unsigned int)j);
                    r += (unsigned int)((bj == b) && (kj > key));
                }
                float e = __expf(x);
                bool i1 = (b < bk1) | ((b == bk1) & (r < K1));
                bool i2 = (b < bk2) | ((b == bk2) & (r < K2));
                bool i3 = (b < bk3) | ((b == bk3) & (r < K3));
                bool i4 = (b < bk4) | ((b == bk4) & (r < K4));
                if ((b == bk1) & (r < K1)) s1 += e;
                if ((b == bk2) & (r < K2)) s2 += e;
                if ((b == bk3) & (r < K3)) s3 += e;
                if ((b == bk4) & (r < K4)) s4 += e;
                ovr[wrow][gidx] = (unsigned char)((unsigned)i1 | ((unsigned)i2 << 1)
                                | ((unsigned)i3 << 2) | ((unsigned)i4 << 3));
            }
        }
    }
    __syncwarp();

    // ---- fused pass: E computed here (short live range); X := exp(x).
    //      min(y,YHI) zeroes the fast path for clamped-high elems even if
    //      bin 0 were a boundary bin (adversarial). Low side safe. ----
    const uint4 B2 = bbs[wrow];
    const float E1 = __uint_as_float(TOPB - (B2.x >> 16));
    const float E2 = __uint_as_float(TOPB - (B2.y >> 16));
    const float E3 = __uint_as_float(TOPB - (B2.z >> 16));
    const float E4 = __uint_as_float(TOPB - (B2.w >> 16));
    {
        float* xv = (float*)X;
        #pragma unroll
        for (int i = 0; i < 16; i++) {
            float x = xv[i];
            float y = fminf(x + OFFF, YHI);
            float e = __expf(x);          // softmax shift-invariant; |x| ~ 5
            xv[i] = e;
            if (y > E1) s1 += e;
            if (y > E2) s2 += e;
            if (y > E3) s3 += e;
            if (y > E4) s4 += e;
        }
    }
    #pragma unroll
    for (int o = 16; o > 0; o >>= 1) {
        s1 += __shfl_xor_sync(0xffffffffu, s1, o);
        s2 += __shfl_xor_sync(0xffffffffu, s2, o);
        s3 += __shfl_xor_sync(0xffffffffu, s3, o);
        s4 += __shfl_xor_sync(0xffffffffu, s4, o);
    }
    const float q1 = __fdividef(__ldg(w1p), s1), q2 = __fdividef(__ldg(w2p), s2),
                q3 = __fdividef(__ldg(w3p), s3), q4 = __fdividef(__ldg(w4p), s4);

    // exp-domain edges for the write pass: non-amb elems are >= 1/256 in x
    // from the bin edge -> >=0.39% relative margin in e (>> MUFU 2-ulp).
    const float F1 = __expf(E1 - OFFF);
    const float F2 = __expf(E2 - OFFF);
    const float F3 = __expf(E3 - OFFF);
    const float F4 = __expf(E4 - OFFF);

    // ---- write: exp-domain compares (exact for all non-amb elements) ----
    {
        const float* ev = (const float*)X;
        float4* op = (float4*)(out + (size_t)row * C);
        #pragma unroll
        for (int g = 0; g < 4; g++) {
            float4 o4;
            float* o = (float*)&o4;
            #pragma unroll
            for (int e = 0; e < 4; e++) {
                float ee = ev[4 * g + e];
                float coef = 0.f;
                if (ee > F1) coef += q1;
                if (ee > F2) coef += q2;
                if (ee > F3) coef += q3;
                if (ee > F4) coef += q4;
                o[e] = ee * coef;
            }
            op[lane + 32 * g] = o4;
        }
    }

    // ---- post-store exact fix for ambiguous elems (1 LDS byte each;
    //      same-thread same-address STG ordering is program order) ----
    if (ambm) {
        const float* ev = (const float*)X;
        float* ob = out + (size_t)row * C;
        unsigned int am = ambm;
        while (am) {
            int i = __ffs(am) - 1; am &= am - 1;
            int gidx = 4 * lane + 128 * (i >> 2) + (i & 3);
            unsigned int bits = ovr[wrow][gidx];
            float cf = 0.f;
            if (bits & 1u) cf += q1;
            if (bits & 2u) cf += q2;
            if (bits & 4u) cf += q3;
            if (bits & 8u) cf += q4;
            ob[gidx] = ev[i] * cf;
        }
    }
}

extern "C" void kernel_launch(void* const* d_in, const int* in_sizes, int n_in,
                              void* d_out, int out_size)
{
    const float* attn = (const float*)d_in[0];
    const float* w1   = (const float*)d_in[1];
    const float* w2   = (const float*)d_in[2];
    const float* w3   = (const float*)d_in[3];
    const float* w4   = (const float*)d_in[4];
    float* out = (float*)d_out;

    int rows   = in_sizes[0] / C;
    int blocks = rows / RPB;
    multiscale_topk_kernel<<<blocks, 32 * RPB>>>(attn, w1, w2, w3, w4, out);
}